// round 14
// baseline (speedup 1.0000x reference)
#include <cuda_runtime.h>
#include <cuda_bf16.h>
#include <math.h>
#include <stdint.h>

// ---------------------------------------------------------------------------
// Problem constants (B=4, C=128, H=W=128, NH=8, d=16, GDFN hidden=512)
// ---------------------------------------------------------------------------
#define BATCH 4
#define CH    128
#define HW    16384
#define NHEAD 8
#define DHEAD 16
#define ALOG_SEGS 128

#if defined(__CUDA_ARCH_FEAT_SM103_ALL) || defined(__CUDA_ARCH_FEAT_SM100_ALL) || defined(__CUDA_ARCH_FAMILY_SPECIFIC__)
#define HAS_TC5 1
#else
#define HAS_TC5 0
#endif

// validated idesc from test_mma.cu: f32 acc, bf16 A/B K-major, M=128, N=32, TS.
#define IDESC_F16 0x8080490u

// ---------------------------------------------------------------------------
// Scratch (device globals)
// ---------------------------------------------------------------------------
__device__ float g_bufA[BATCH * 512 * HW];
__device__ float g_bufB[BATCH * 512 * HW];
__device__ float g_mu  [BATCH * HW];
__device__ float g_rstd[BATCH * HW];
__device__ float g_partS [32 * ALOG_SEGS * 256];
__device__ float g_partQ2[32 * ALOG_SEGS * 16];
__device__ float g_partK2[32 * ALOG_SEGS * 16];
__device__ float g_attn  [32 * 256];
__device__ float g_WqP [384 * 128];
__device__ float g_Wg1P[512 * 128];
__device__ float g_Wg2P[128 * 256];
__device__ float g_Weff[BATCH * 128 * 128];
__device__ uint8_t g_WqT  [12 * 16384];        // qkv: 12 groups of 32 oc, [hi|lo] K=128
__device__ uint8_t g_Wg1T [16 * 16384];
__device__ uint8_t g_Wg2T [4 * 32768];         // K=256
__device__ uint8_t g_WeffT[BATCH * 4 * 16384];
__device__ float g_rs[896];
__device__ float g_cb[896];

// ---------------------------------------------------------------------------
// generic helpers
// ---------------------------------------------------------------------------
__device__ __forceinline__ void cp16(uint32_t dst_smem, const void* src)
{
    asm volatile("cp.async.ca.shared.global [%0], [%1], 16;" :: "r"(dst_smem), "l"(src));
}
__device__ __forceinline__ void cp_commit() { asm volatile("cp.async.commit_group;"); }
template <int N>
__device__ __forceinline__ void cp_wait() { asm volatile("cp.async.wait_group %0;" :: "n"(N)); }

__device__ __forceinline__ float gelu_exact(float v)
{
    return 0.5f * v * (1.f + erff(v * 0.70710678118654752440f));
}

// blocked-atom + SW128 byte offset within one 32-row tile (validated,
// test_mma_iter: atom_offset = atom_row + atom_col*4).
__device__ __forceinline__ uint32_t img_off(int brow, int kk)
{
    uint32_t off = (uint32_t)(((brow >> 3) + (kk >> 6) * 4) * 1024
                 + (brow & 7) * 128 + (kk & 63) * 2);
    return off ^ ((off >> 3) & 0x70);
}

#if HAS_TC5
// ---------------------------------------------------------------------------
// tcgen05 helpers — all from validated examples
// ---------------------------------------------------------------------------
__device__ __forceinline__ uint32_t elect_one_pred()
{
    uint32_t pred;
    asm volatile("{\n\t.reg .pred p;\n\telect.sync _|p, 0xFFFFFFFF;\n\t"
                 "selp.b32 %0, 1, 0, p;\n\t}" : "=r"(pred));
    return pred;
}
#define TC5_ALLOC(sptr, n)   asm volatile("tcgen05.alloc.cta_group::1.sync.aligned.shared::cta.b32 [%0], %1;" :: "r"(sptr), "r"(n) : "memory")
#define TC5_DEALLOC(t, n)    asm volatile("tcgen05.dealloc.cta_group::1.sync.aligned.b32 %0, %1;" :: "r"(t), "r"(n))
#define TC5_COMMIT(mb)       asm volatile("tcgen05.commit.cta_group::1.mbarrier::arrive::one.shared::cluster.b64 [%0];" :: "r"(mb) : "memory")
#define TC5_WAIT_LD()        asm volatile("tcgen05.wait::ld.sync.aligned;" ::: "memory")
#define TC5_WAIT_ST()        asm volatile("tcgen05.wait::st.sync.aligned;" ::: "memory")
#define TC5_FENCE_BEFORE()   asm volatile("tcgen05.fence::before_thread_sync;" ::: "memory")
#define TC5_FENCE_AFTER()    asm volatile("tcgen05.fence::after_thread_sync;" ::: "memory")
#define FENCE_ASYNC()        asm volatile("fence.proxy.async.shared::cta;" ::: "memory")
#define MBAR_INIT(mb, c)     asm volatile("mbarrier.init.shared.b64 [%0], %1;" :: "r"(mb), "r"(c) : "memory")
#define MBAR_INVAL(mb)       asm volatile("mbarrier.inval.shared.b64 [%0];" :: "r"(mb) : "memory")

#define MBAR_WAIT(mb, par) do {                                                    \
    uint32_t _mb = (mb), _p = (par), _d;                                           \
    asm volatile("{\n\t.reg .pred p;\n\t"                                          \
        "mbarrier.try_wait.parity.acquire.cta.shared::cta.b64 p, [%1], %2;\n\t"    \
        "selp.b32 %0, 1, 0, p;\n\t}" : "=r"(_d) : "r"(_mb), "r"(_p) : "memory");   \
    if (!_d) {                                                                     \
        asm volatile("{\n\t.reg .pred P1;\n\t"                                     \
            "WL_%=:\n\t"                                                           \
            "mbarrier.try_wait.parity.acquire.cta.shared::cta.b64 P1, [%0], %1, 0x989680;\n\t" \
            "@P1 bra.uni WD_%=;\n\tbra.uni WL_%=;\n\tWD_%=:\n\t}"                  \
            :: "r"(_mb), "r"(_p) : "memory");                                      \
    }                                                                              \
} while (0)

#define TC5_LD_X32(r, a)                                                           \
    asm volatile("tcgen05.ld.sync.aligned.32x32b.x32.b32 "                         \
        "{%0,%1,%2,%3,%4,%5,%6,%7,%8,%9,%10,%11,%12,%13,%14,%15,"                  \
        "%16,%17,%18,%19,%20,%21,%22,%23,%24,%25,%26,%27,%28,%29,%30,%31}, [%32];" \
        : "=r"((r)[0]),"=r"((r)[1]),"=r"((r)[2]),"=r"((r)[3]),                     \
          "=r"((r)[4]),"=r"((r)[5]),"=r"((r)[6]),"=r"((r)[7]),                     \
          "=r"((r)[8]),"=r"((r)[9]),"=r"((r)[10]),"=r"((r)[11]),                   \
          "=r"((r)[12]),"=r"((r)[13]),"=r"((r)[14]),"=r"((r)[15]),                 \
          "=r"((r)[16]),"=r"((r)[17]),"=r"((r)[18]),"=r"((r)[19]),                 \
          "=r"((r)[20]),"=r"((r)[21]),"=r"((r)[22]),"=r"((r)[23]),                 \
          "=r"((r)[24]),"=r"((r)[25]),"=r"((r)[26]),"=r"((r)[27]),                 \
          "=r"((r)[28]),"=r"((r)[29]),"=r"((r)[30]),"=r"((r)[31])                  \
        : "r"(a))

#define TC5_ST_X32(tmem_addr, r)                                                   \
    asm volatile("tcgen05.st.sync.aligned.32x32b.x32.b32 [%0], "                   \
        "{%1,%2,%3,%4,%5,%6,%7,%8,%9,%10,%11,%12,%13,%14,%15,%16,"                 \
        "%17,%18,%19,%20,%21,%22,%23,%24,%25,%26,%27,%28,%29,%30,%31,%32};"        \
        :: "r"(tmem_addr),                                                         \
           "r"((r)[0]),"r"((r)[1]),"r"((r)[2]),"r"((r)[3]),                        \
           "r"((r)[4]),"r"((r)[5]),"r"((r)[6]),"r"((r)[7]),                        \
           "r"((r)[8]),"r"((r)[9]),"r"((r)[10]),"r"((r)[11]),                      \
           "r"((r)[12]),"r"((r)[13]),"r"((r)[14]),"r"((r)[15]),                    \
           "r"((r)[16]),"r"((r)[17]),"r"((r)[18]),"r"((r)[19]),                    \
           "r"((r)[20]),"r"((r)[21]),"r"((r)[22]),"r"((r)[23]),                    \
           "r"((r)[24]),"r"((r)[25]),"r"((r)[26]),"r"((r)[27]),                    \
           "r"((r)[28]),"r"((r)[29]),"r"((r)[30]),"r"((r)[31])                     \
        : "memory")

__device__ __forceinline__ void tc5_mma_f16(uint32_t d_tmem, uint32_t a_tmem,
                                            uint64_t b_desc, uint32_t acc)
{
    asm volatile(
        "{\n\t.reg .pred p;\n\tsetp.ne.u32 p, %4, 0;\n\t"
        "tcgen05.mma.cta_group::1.kind::f16 [%0], [%1], %2, %3, {%5,%5,%5,%5}, p;\n\t}"
        :: "r"(d_tmem), "r"(a_tmem), "l"(b_desc), "r"(IDESC_F16), "r"(acc), "r"(0u)
        : "memory");
}
__device__ __forceinline__ uint64_t mk_desc(uint32_t addr)
{
    return ((uint64_t)2 << 61) | (1ull << 46) | (64ull << 32) | (1ull << 16)
         | ((uint64_t)(addr >> 4) & 0x3FFF);
}
#endif  // HAS_TC5

// ---------------------------------------------------------------------------
// 0a) Weight prep: LN-scale, hi/lo bf16 split, swizzled tile images, rowsum/cb.
// ---------------------------------------------------------------------------
__global__ __launch_bounds__(256) void prep_w_k(const float* __restrict__ qkv_pw,
                                                const float* __restrict__ ln1w,
                                                const float* __restrict__ ln1b,
                                                const float* __restrict__ g1w,
                                                const float* __restrict__ ln2w,
                                                const float* __restrict__ ln2b,
                                                const float* __restrict__ g2w)
{
    int row  = blockIdx.x * 8 + (threadIdx.x >> 5);
    int lane = threadIdx.x & 31;

    if (row < 896) {
        const float *W, *lw, *lb;
        float* Wp;
        uint8_t* img;
        int rl;
        if (row < 384) {
            W = qkv_pw + (size_t)row * 128; lw = ln1w; lb = ln1b;
            Wp = g_WqP + (size_t)row * 128; rl = row;
            img = g_WqT + (size_t)(rl >> 5) * 16384;
        } else {
            rl = row - 384;
            W = g1w + (size_t)rl * 128; lw = ln2w; lb = ln2b;
            Wp = g_Wg1P + (size_t)rl * 128;
            img = g_Wg1T + (size_t)(rl >> 5) * 16384;
        }
        int brow = rl & 31;
        float rs = 0.f, cb = 0.f;
#pragma unroll
        for (int t = 0; t < 4; t++) {
            int c = lane + t * 32;
            float w = W[c];
            float wp = w * lw[c];
            Wp[c] = wp;
            __nv_bfloat16 hb = __float2bfloat16(wp);
            __nv_bfloat16 lbv = __float2bfloat16(wp - __bfloat162float(hb));
            *(__nv_bfloat16*)(img + img_off(brow, c))       = hb;
            *(__nv_bfloat16*)(img + img_off(brow, 128 + c)) = lbv;
            rs += __bfloat162float(hb) + __bfloat162float(lbv);
            cb += w * lb[c];
        }
#pragma unroll
        for (int o = 16; o > 0; o >>= 1) {
            rs += __shfl_xor_sync(0xffffffffu, rs, o);
            cb += __shfl_xor_sync(0xffffffffu, cb, o);
        }
        if (lane == 0) { g_rs[row] = rs; g_cb[row] = cb; }
    } else {
        int r = row - 896;
        uint8_t* img = g_Wg2T + (size_t)(r >> 5) * 32768;
        int brow = r & 31;
#pragma unroll
        for (int t = 0; t < 8; t++) {
            int c = lane + t * 32;
            float w = g2w[r * 256 + c];
            g_Wg2P[r * 256 + c] = w;
            __nv_bfloat16 hb = __float2bfloat16(w);
            __nv_bfloat16 lbv = __float2bfloat16(w - __bfloat162float(hb));
            *(__nv_bfloat16*)(img + img_off(brow, c))       = hb;
            *(__nv_bfloat16*)(img + img_off(brow, 256 + c)) = lbv;
        }
    }
}

// ---------------------------------------------------------------------------
// 0b) Per-pixel LayerNorm stats
// ---------------------------------------------------------------------------
__global__ __launch_bounds__(256) void ln_stats_k(const float* __restrict__ x,
                                                  float* __restrict__ mu,
                                                  float* __restrict__ rstd)
{
    int b  = blockIdx.y;
    int n4 = blockIdx.x * 256 + threadIdx.x;
    const float4* xb = (const float4*)(x + (size_t)b * CH * HW) + n4;
    float4 s  = make_float4(0.f, 0.f, 0.f, 0.f);
    float4 s2 = make_float4(0.f, 0.f, 0.f, 0.f);
#pragma unroll 8
    for (int c = 0; c < CH; c++) {
        float4 v = xb[(size_t)c * (HW / 4)];
        s.x += v.x; s.y += v.y; s.z += v.z; s.w += v.w;
        s2.x = fmaf(v.x, v.x, s2.x); s2.y = fmaf(v.y, v.y, s2.y);
        s2.z = fmaf(v.z, v.z, s2.z); s2.w = fmaf(v.w, v.w, s2.w);
    }
    float4 m, r;
    m.x = s.x * (1.f / CH); m.y = s.y * (1.f / CH);
    m.z = s.z * (1.f / CH); m.w = s.w * (1.f / CH);
    r.x = rsqrtf(s2.x * (1.f / CH) - m.x * m.x + 1e-5f);
    r.y = rsqrtf(s2.y * (1.f / CH) - m.y * m.y + 1e-5f);
    r.z = rsqrtf(s2.z * (1.f / CH) - m.z * m.z + 1e-5f);
    r.w = rsqrtf(s2.w * (1.f / CH) - m.w * m.w + 1e-5f);
    *(float4*)&mu  [b * HW + n4 * 4] = m;
    *(float4*)&rstd[b * HW + n4 * 4] = r;
}

// ---------------------------------------------------------------------------
// 1) GEMM via validated tcgen05 bf16 TS recipe, hi/lo split (3 passes).
//    Lean version: 64-row X staging, single B buffer, 256-col TMEM (K=128)
//    -> 2 CTAs/SM with both CTAs' TMEM resident. Grid (HW/128, BATCH).
// ---------------------------------------------------------------------------
template <int MODE, bool RESID, int K, int OCT>
__global__ __launch_bounds__(256) void gemm5(
    const uint8_t* __restrict__ Bimg, size_t bimg_stride,
    const float* __restrict__ Wplain, int wp_stride,
    const float* __restrict__ X,
    const float* __restrict__ mu, const float* __restrict__ rstd,
    const float* __restrict__ rsum, const float* __restrict__ cbias,
    const float* __restrict__ resid,
    float* __restrict__ out, int OC, int XCH)
{
    extern __shared__ uint8_t dsm[];
    const int b = blockIdx.y, n0 = blockIdx.x * 128;
    const int tid = threadIdx.x, warp = tid >> 5, lane = tid & 31;
    const float* Xb = X + (size_t)b * XCH * HW;

    constexpr int KC    = K / 64;           // X convert chunks (64 k-rows each)
    constexpr int TILEB = 128 * K;          // bytes per 32-oc group image
    constexpr int OCB   = 4 * TILEB;        // bytes per 128-oc tile
    constexpr int ALOC  = K / 2;            // TMEM col base of Xlo
    constexpr int STEPS = K / 16;           // K-steps per pass
    constexpr int DBASE = K;                // TMEM col base of D
    constexpr int NCOLS = (K == 128) ? 256 : 512;
    constexpr int XSTG  = 64 * 132 * 4;     // 33792 bytes

    uint8_t* al = (uint8_t*)(((uintptr_t)dsm + 1023) & ~(uintptr_t)1023);
    float* XSp = (float*)al;
    const uint32_t xs = (uint32_t)__cvta_generic_to_shared(al);
    const uint32_t bs = xs + XSTG;

#if HAS_TC5
    const uint8_t* Bb = Bimg + (size_t)b * bimg_stride;
    __shared__ uint32_t s_tmem;
    __shared__ __align__(8) uint64_t s_mbar;
    const uint32_t sptr = (uint32_t)__cvta_generic_to_shared(&s_tmem);
    const uint32_t mbar = (uint32_t)__cvta_generic_to_shared(&s_mbar);

    if (warp == 0) TC5_ALLOC(sptr, NCOLS);
    if (tid == 0) MBAR_INIT(mbar, 1);
    __syncthreads();
    uint32_t tmem;
    asm volatile("ld.shared.b32 %0, [%1];" : "=r"(tmem) : "r"(sptr));

    auto loadB = [&](int t) {
        const uint8_t* src = Bb + (size_t)t * OCB;
        for (int i = tid; i < OCB / 16; i += 256)
            cp16(bs + i * 16, src + (size_t)i * 16);
        cp_commit();
    };

    // prologue: B(0) + X staged/converted 64 rows at a time
    loadB(0);
    for (int c = 0; c < KC; c++) {
        for (int i = tid; i < 64 * 32; i += 256) {       // 2048 float4
            int kk = i >> 5, c4 = (i & 31) << 2;
            cp16(xs + (uint32_t)(kk * 132 + c4) * 4,
                 &Xb[(size_t)(c * 64 + kk) * HW + n0 + c4]);
        }
        cp_commit();
        cp_wait<0>();
        __syncthreads();
        if (tid < 128) {
            int px = tid;
            uint32_t woff = (uint32_t)(tid >> 5) << 21;
            uint32_t v[32];
#pragma unroll
            for (int i = 0; i < 32; i++) {               // hi
                float x0 = XSp[(2 * i) * 132 + px];
                float x1 = XSp[(2 * i + 1) * 132 + px];
                __nv_bfloat162 h;
                h.x = __float2bfloat16(x0);
                h.y = __float2bfloat16(x1);
                v[i] = *(uint32_t*)&h;
            }
            TC5_ST_X32(tmem + c * 32 + woff, v);
            TC5_WAIT_ST();
#pragma unroll
            for (int i = 0; i < 32; i++) {               // lo
                float x0 = XSp[(2 * i) * 132 + px];
                float x1 = XSp[(2 * i + 1) * 132 + px];
                __nv_bfloat16 h0 = __float2bfloat16(x0);
                __nv_bfloat16 h1 = __float2bfloat16(x1);
                __nv_bfloat162 l;
                l.x = __float2bfloat16(x0 - __bfloat162float(h0));
                l.y = __float2bfloat16(x1 - __bfloat162float(h1));
                v[i] = *(uint32_t*)&l;
            }
            TC5_ST_X32(tmem + ALOC + c * 32 + woff, v);
            TC5_WAIT_ST();
        }
        __syncthreads();
    }
    FENCE_ASYNC();

    // main loop over oc-tiles (single B buffer; B(t+1) load overlaps epilogue)
    for (int t = 0; t < OCT; t++) {
        if (warp == 0) {
            TC5_FENCE_AFTER();
            if (elect_one_pred()) {
#pragma unroll
                for (int g = 0; g < 4; g++) {
                    uint64_t bd = mk_desc(bs + g * TILEB);
                    uint32_t dreg = tmem + DBASE + g * 32;
#pragma unroll
                    for (int pass = 0; pass < 3; pass++) {
                        uint32_t abase = (pass == 1) ? (uint32_t)ALOC : 0u;
                        int tb0 = (pass == 2) ? STEPS : 0;
#pragma unroll
                        for (int s = 0; s < STEPS; s++) {
                            int tb = tb0 + s;
                            uint64_t bo = (uint64_t)((tb >> 2) * 256 + (tb & 3) * 2);
                            tc5_mma_f16(dreg, tmem + abase + s * 8, bd + bo,
                                        (pass == 0 && s == 0) ? 0u : 1u);
                        }
                    }
                }
                TC5_COMMIT(mbar);
            }
        }
        MBAR_WAIT(mbar, t & 1);
        TC5_FENCE_AFTER();
        if (t + 1 < OCT) loadB(t + 1);                    // B consumed: safe; overlaps epilogue

        // epilogue: lane -> px, cols -> oc
        {
            int px  = (warp & 3) * 32 + lane;
            int cb0 = (warp >> 2) * 64;
            float mpx = 0.f, rpx = 0.f;
            if (MODE == 1) { mpx = mu[b * HW + n0 + px]; rpx = rstd[b * HW + n0 + px]; }
#pragma unroll
            for (int h2 = 0; h2 < 2; h2++) {
                uint32_t dr[32];
                TC5_LD_X32(dr, tmem + DBASE + cb0 + h2 * 32);
                TC5_WAIT_LD();
                int ocb = t * 128 + cb0 + h2 * 32;
#pragma unroll
                for (int i = 0; i < 32; i++) {
                    int oc = ocb + i;
                    float v = __uint_as_float(dr[i]);
                    if (MODE == 1) v = rpx * (v - mpx * rsum[oc]) + cbias[oc];
                    size_t o = ((size_t)b * OC + oc) * HW + n0 + px;
                    if (RESID) v += resid[o];
                    out[o] = v;
                }
            }
            TC5_FENCE_BEFORE();
        }
        if (t + 1 < OCT) {
            cp_wait<0>();
            __syncthreads();
            FENCE_ASYNC();
        }
    }

    if (tid == 0) MBAR_INVAL(mbar);
    __syncthreads();
    if (warp == 0) TC5_DEALLOC(tmem, NCOLS);

#else
    // ---- fallback: plain FFMA tile GEMM (correct; unused on sm_103a) ----
    (void)Bimg; (void)bimg_stride;
    const float* Wb = Wplain + (size_t)b * wp_stride;
    float* WSp = (float*)(al + XSTG);       // 128 oc x 68 k floats
    int tx = tid & 15, ty = tid >> 4;

    for (int t = 0; t < OCT; t++) {
        float acc[8][8];
#pragma unroll
        for (int u = 0; u < 8; u++)
#pragma unroll
            for (int v = 0; v < 8; v++) acc[u][v] = 0.f;

        for (int c = 0; c < KC; c++) {
            __syncthreads();
            for (int i = tid; i < 64 * 32; i += 256) {
                int kk = i >> 5, c4 = (i & 31) << 2;
                *(float4*)&XSp[kk * 132 + c4] =
                    *(const float4*)&Xb[(size_t)(c * 64 + kk) * HW + n0 + c4];
            }
            for (int i = tid; i < 128 * 16; i += 256) {
                int oc = i >> 4, k4 = (i & 15) << 2;
                *(float4*)&WSp[oc * 68 + k4] =
                    *(const float4*)&Wb[(size_t)(t * 128 + oc) * K + c * 64 + k4];
            }
            __syncthreads();
            for (int k = 0; k < 64; k++) {
                float a[8], bv[8];
#pragma unroll
                for (int u = 0; u < 8; u++) a[u]  = WSp[(ty * 8 + u) * 68 + k];
#pragma unroll
                for (int v = 0; v < 8; v++) bv[v] = XSp[k * 132 + tx * 8 + v];
#pragma unroll
                for (int u = 0; u < 8; u++)
#pragma unroll
                    for (int v = 0; v < 8; v++)
                        acc[u][v] = fmaf(a[u], bv[v], acc[u][v]);
            }
        }
#pragma unroll
        for (int u = 0; u < 8; u++) {
            int oc = t * 128 + ty * 8 + u;
            float rsv = 0.f, cbv = 0.f;
            if (MODE == 1) { rsv = rsum[oc]; cbv = cbias[oc]; }
#pragma unroll
            for (int v = 0; v < 8; v++) {
                int px = tx * 8 + v;
                float r = acc[u][v];
                if (MODE == 1)
                    r = rstd[b * HW + n0 + px] * (r - mu[b * HW + n0 + px] * rsv) + cbv;
                size_t o = ((size_t)b * OC + oc) * HW + n0 + px;
                if (RESID) r += resid[o];
                out[o] = r;
            }
        }
        __syncthreads();
    }
#endif
}

// ---------------------------------------------------------------------------
// 2) Depthwise 3x3 conv
// ---------------------------------------------------------------------------
__global__ __launch_bounds__(256) void dwconv_k(const float* __restrict__ in,
                                                const float* __restrict__ wd,
                                                float* __restrict__ out,
                                                int CHN)
{
    __shared__ float t[18][136];
    int plane = blockIdx.y;
    int ch    = plane % CHN;
    size_t base = (size_t)plane * HW;
    int y0  = blockIdx.x * 16;
    int tid = threadIdx.x;

    if (tid < 36) t[tid >> 1][3 + (tid & 1) * 129] = 0.f;
#pragma unroll
    for (int i = tid; i < 576; i += 256) {
        int r = i >> 5, c4 = (i & 31) << 2;
        int gy = y0 - 1 + r;
        float4 v = make_float4(0.f, 0.f, 0.f, 0.f);
        if (gy >= 0 && gy < 128) v = *(const float4*)&in[base + gy * 128 + c4];
        *(float4*)&t[r][4 + c4] = v;
    }
    __syncthreads();

    float w[9];
#pragma unroll
    for (int j = 0; j < 9; j++) w[j] = wd[ch * 9 + j];

    int x4 = (tid & 31) << 2;
    int r0 = tid >> 5;
#pragma unroll
    for (int rr = 0; rr < 16; rr += 8) {
        int row = r0 + rr;
        float4 o = make_float4(0.f, 0.f, 0.f, 0.f);
#pragma unroll
        for (int dy = 0; dy < 3; dy++) {
            const float* tr = &t[row + dy][4 + x4];
            float m0 = tr[-1], m1 = tr[0], m2 = tr[1], m3 = tr[2], m4 = tr[3], m5 = tr[4];
            float a = w[dy * 3 + 0], bw = w[dy * 3 + 1], c = w[dy * 3 + 2];
            o.x = fmaf(a, m0, fmaf(bw, m1, fmaf(c, m2, o.x)));
            o.y = fmaf(a, m1, fmaf(bw, m2, fmaf(c, m3, o.y)));
            o.z = fmaf(a, m2, fmaf(bw, m3, fmaf(c, m4, o.z)));
            o.w = fmaf(a, m3, fmaf(bw, m4, fmaf(c, m5, o.w)));
        }
        *(float4*)&out[base + (y0 + row) * 128 + x4] = o;
    }
}

// ---------------------------------------------------------------------------
// 2b) GDFN: dwconv of x1/x2 + gelu gate, fused
// ---------------------------------------------------------------------------
__global__ __launch_bounds__(256) void dwgate_k(const float* __restrict__ in,
                                                const float* __restrict__ wd,
                                                float* __restrict__ out)
{
    __shared__ float t1[18][136];
    __shared__ float t2[18][136];
    int plane = blockIdx.y;
    int b  = plane >> 8, ch = plane & 255;
    size_t base1 = ((size_t)b * 512 + ch) * HW;
    size_t base2 = ((size_t)b * 512 + 256 + ch) * HW;
    size_t baseo = ((size_t)b * 256 + ch) * HW;
    int y0  = blockIdx.x * 16;
    int tid = threadIdx.x;

    if (tid < 36) {
        t1[tid >> 1][3 + (tid & 1) * 129] = 0.f;
        t2[tid >> 1][3 + (tid & 1) * 129] = 0.f;
    }
#pragma unroll
    for (int i = tid; i < 576; i += 256) {
        int r = i >> 5, c4 = (i & 31) << 2;
        int gy = y0 - 1 + r;
        float4 v1 = make_float4(0.f, 0.f, 0.f, 0.f);
        float4 v2 = make_float4(0.f, 0.f, 0.f, 0.f);
        if (gy >= 0 && gy < 128) {
            v1 = *(const float4*)&in[base1 + gy * 128 + c4];
            v2 = *(const float4*)&in[base2 + gy * 128 + c4];
        }
        *(float4*)&t1[r][4 + c4] = v1;
        *(float4*)&t2[r][4 + c4] = v2;
    }
    __syncthreads();

    float wA[9], wB[9];
#pragma unroll
    for (int j = 0; j < 9; j++) { wA[j] = wd[ch * 9 + j]; wB[j] = wd[(256 + ch) * 9 + j]; }

    int x4 = (tid & 31) << 2;
    int r0 = tid >> 5;
#pragma unroll
    for (int rr = 0; rr < 16; rr += 8) {
        int row = r0 + rr;
        float4 o1 = make_float4(0.f, 0.f, 0.f, 0.f);
        float4 o2 = make_float4(0.f, 0.f, 0.f, 0.f);
#pragma unroll
        for (int dy = 0; dy < 3; dy++) {
            {
                const float* tr = &t1[row + dy][4 + x4];
                float m0 = tr[-1], m1 = tr[0], m2 = tr[1], m3 = tr[2], m4 = tr[3], m5 = tr[4];
                float a = wA[dy * 3 + 0], bw = wA[dy * 3 + 1], c = wA[dy * 3 + 2];
                o1.x = fmaf(a, m0, fmaf(bw, m1, fmaf(c, m2, o1.x)));
                o1.y = fmaf(a, m1, fmaf(bw, m2, fmaf(c, m3, o1.y)));
                o1.z = fmaf(a, m2, fmaf(bw, m3, fmaf(c, m4, o1.z)));
                o1.w = fmaf(a, m3, fmaf(bw, m4, fmaf(c, m5, o1.w)));
            }
            {
                const float* tr = &t2[row + dy][4 + x4];
                float m0 = tr[-1], m1 = tr[0], m2 = tr[1], m3 = tr[2], m4 = tr[3], m5 = tr[4];
                float a = wB[dy * 3 + 0], bw = wB[dy * 3 + 1], c = wB[dy * 3 + 2];
                o2.x = fmaf(a, m0, fmaf(bw, m1, fmaf(c, m2, o2.x)));
                o2.y = fmaf(a, m1, fmaf(bw, m2, fmaf(c, m3, o2.y)));
                o2.z = fmaf(a, m2, fmaf(bw, m3, fmaf(c, m4, o2.z)));
                o2.w = fmaf(a, m3, fmaf(bw, m4, fmaf(c, m5, o2.w)));
            }
        }
        float4 g;
        g.x = gelu_exact(o1.x) * o2.x;
        g.y = gelu_exact(o1.y) * o2.y;
        g.z = gelu_exact(o1.z) * o2.z;
        g.w = gelu_exact(o1.w) * o2.w;
        *(float4*)&out[baseo + (y0 + row) * 128 + x4] = g;
    }
}

// ---------------------------------------------------------------------------
// 3) Attention logits (float4 loads) + fused sq-norm partials
// ---------------------------------------------------------------------------
__global__ __launch_bounds__(256) void attn_logits_k(const float* __restrict__ qkv)
{
    int seg = blockIdx.x;
    int bh  = blockIdx.y;
    int b = bh >> 3, h = bh & 7;
    const float* qb = qkv + ((size_t)b * 384 + h * DHEAD) * HW + seg * 128;
    const float* kb = qkv + ((size_t)b * 384 + 128 + h * DHEAD) * HW + seg * 128;

    __shared__ __align__(16) float qs[16][132];
    __shared__ __align__(16) float ks[16][132];

    int tid = threadIdx.x;
#pragma unroll
    for (int t = 0; t < 2; t++) {
        int idx = tid + t * 256;
        int row = idx >> 5, c4 = (idx & 31) << 2;
        *(float4*)&qs[row][c4] = *(const float4*)&qb[(size_t)row * HW + c4];
        *(float4*)&ks[row][c4] = *(const float4*)&kb[(size_t)row * HW + c4];
    }
    __syncthreads();

    int i = tid >> 4, j = tid & 15;
    bool diag = (i == j);
    const float4* q4 = (const float4*)&qs[i][0];
    const float4* k4 = (const float4*)&ks[j][0];
    float acc = 0.f, q2 = 0.f, k2 = 0.f;
#pragma unroll 8
    for (int n4 = 0; n4 < 32; n4++) {
        float4 a = q4[n4];
        float4 c = k4[n4];
        acc = fmaf(a.x, c.x, acc); acc = fmaf(a.y, c.y, acc);
        acc = fmaf(a.z, c.z, acc); acc = fmaf(a.w, c.w, acc);
        if (diag) {
            q2 = fmaf(a.x, a.x, q2); q2 = fmaf(a.y, a.y, q2);
            q2 = fmaf(a.z, a.z, q2); q2 = fmaf(a.w, a.w, q2);
            k2 = fmaf(c.x, c.x, k2); k2 = fmaf(c.y, c.y, k2);
            k2 = fmaf(c.z, c.z, k2); k2 = fmaf(c.w, c.w, k2);
        }
    }

    int slot = bh * ALOG_SEGS + seg;
    g_partS[(size_t)slot * 256 + tid] = acc;
    if (diag) {
        g_partQ2[slot * 16 + i] = q2;
        g_partK2[slot * 16 + i] = k2;
    }
}

// ---------------------------------------------------------------------------
// 4) Finalize: reduce segments, l2norm scale, temperature, softmax
// ---------------------------------------------------------------------------
__global__ __launch_bounds__(256) void attn_finalize_k(const float* __restrict__ temp)
{
    int bh = blockIdx.x;
    int h = bh & 7;
    int i = threadIdx.x >> 4, j = threadIdx.x & 15;

    float s = 0.f, q2 = 0.f, k2 = 0.f;
    for (int seg = 0; seg < ALOG_SEGS; seg++) {
        int slot = bh * ALOG_SEGS + seg;
        s  += g_partS [(size_t)slot * 256 + threadIdx.x];
        q2 += g_partQ2[slot * 16 + i];
        k2 += g_partK2[slot * 16 + j];
    }
    float rq = 1.f / fmaxf(sqrtf(q2), 1e-12f);
    float rk = 1.f / fmaxf(sqrtf(k2), 1e-12f);
    s = s * rq * rk * temp[h];

    float m = s;
    m = fmaxf(m, __shfl_xor_sync(0xffffffffu, m, 8, 16));
    m = fmaxf(m, __shfl_xor_sync(0xffffffffu, m, 4, 16));
    m = fmaxf(m, __shfl_xor_sync(0xffffffffu, m, 2, 16));
    m = fmaxf(m, __shfl_xor_sync(0xffffffffu, m, 1, 16));
    float e = expf(s - m);
    float sum = e;
    sum += __shfl_xor_sync(0xffffffffu, sum, 8, 16);
    sum += __shfl_xor_sync(0xffffffffu, sum, 4, 16);
    sum += __shfl_xor_sync(0xffffffffu, sum, 2, 16);
    sum += __shfl_xor_sync(0xffffffffu, sum, 1, 16);
    g_attn[bh * 256 + threadIdx.x] = e / sum;
}

// ---------------------------------------------------------------------------
// 5) Effective proj weights: plain fp32 + swizzled bf16 hi/lo images
// ---------------------------------------------------------------------------
__global__ __launch_bounds__(256) void weff_k(const float* __restrict__ proj_w)
{
    int b = blockIdx.x, h = blockIdx.y;
    __shared__ float at[16][16];
    __shared__ float pw[128][16];
    int tid = threadIdx.x;

    at[tid >> 4][tid & 15] = g_attn[(b * 8 + h) * 256 + tid];
#pragma unroll
    for (int t = 0; t < 8; t++) {
        int idx = tid + t * 256;
        int o = idx >> 4, i = idx & 15;
        pw[o][i] = proj_w[o * 128 + h * 16 + i];
    }
    __syncthreads();

    uint8_t* imgb = g_WeffT + (size_t)b * 4 * 16384;
#pragma unroll
    for (int t = 0; t < 8; t++) {
        int idx = tid + t * 256;
        int o = idx >> 4, e = idx & 15;
        float s = 0.f;
#pragma unroll
        for (int i = 0; i < 16; i++) s = fmaf(pw[o][i], at[i][e], s);
        g_Weff[((size_t)b * 128 + o) * 128 + h * 16 + e] = s;
        __nv_bfloat16 hb = __float2bfloat16(s);
        __nv_bfloat16 lb = __float2bfloat16(s - __bfloat162float(hb));
        uint8_t* img = imgb + (size_t)(o >> 5) * 16384;
        int brow = o & 31, kk = h * 16 + e;
        *(__nv_bfloat16*)(img + img_off(brow, kk))       = hb;
        *(__nv_bfloat16*)(img + img_off(brow, 128 + kk)) = lb;
    }
}

// ---------------------------------------------------------------------------
// Launch
// ---------------------------------------------------------------------------
extern "C" void kernel_launch(void* const* d_in, const int* in_sizes, int n_in,
                              void* d_out, int out_size)
{
    const float* x      = (const float*)d_in[0];
    const float* ln1_w  = (const float*)d_in[1];
    const float* ln1_b  = (const float*)d_in[2];
    const float* temp   = (const float*)d_in[3];
    const float* qkv_pw = (const float*)d_in[4];
    const float* qkv_dw = (const float*)d_in[5];
    const float* proj_w = (const float*)d_in[6];
    const float* ln2_w  = (const float*)d_in[7];
    const float* ln2_b  = (const float*)d_in[8];
    const float* g1_w   = (const float*)d_in[9];
    const float* gd_w   = (const float*)d_in[10];
    const float* g2_w   = (const float*)d_in[11];
    float* out = (float*)d_out;

    float *bufA, *bufB, *WqP, *Wg1P, *Wg2P, *rs, *cb, *Weff, *mu, *rstd;
    uint8_t *WqT, *Wg1T, *Wg2T, *WeffT;
    cudaGetSymbolAddress((void**)&bufA,  g_bufA);
    cudaGetSymbolAddress((void**)&bufB,  g_bufB);
    cudaGetSymbolAddress((void**)&WqP,   g_WqP);
    cudaGetSymbolAddress((void**)&Wg1P,  g_Wg1P);
    cudaGetSymbolAddress((void**)&Wg2P,  g_Wg2P);
    cudaGetSymbolAddress((void**)&rs,    g_rs);
    cudaGetSymbolAddress((void**)&cb,    g_cb);
    cudaGetSymbolAddress((void**)&Weff,  g_Weff);
    cudaGetSymbolAddress((void**)&mu,    g_mu);
    cudaGetSymbolAddress((void**)&rstd,  g_rstd);
    cudaGetSymbolAddress((void**)&WqT,   g_WqT);
    cudaGetSymbolAddress((void**)&Wg1T,  g_Wg1T);
    cudaGetSymbolAddress((void**)&Wg2T,  g_Wg2T);
    cudaGetSymbolAddress((void**)&WeffT, g_WeffT);

    const int sm_128 = 33792 + 65536 + 1024;    // 100,352 -> 2 blocks/SM
    const int sm_g2  = 33792 + 131072 + 1024;   // 165,888 -> 1 block/SM
    cudaFuncSetAttribute(gemm5<1, false, 128, 3>, cudaFuncAttributeMaxDynamicSharedMemorySize, sm_128);
    cudaFuncSetAttribute(gemm5<1, false, 128, 4>, cudaFuncAttributeMaxDynamicSharedMemorySize, sm_128);
    cudaFuncSetAttribute(gemm5<0, true, 128, 1>,  cudaFuncAttributeMaxDynamicSharedMemorySize, sm_128);
    cudaFuncSetAttribute(gemm5<0, true, 256, 1>,  cudaFuncAttributeMaxDynamicSharedMemorySize, sm_g2);

    dim3 b256(256);
    dim3 ggrid(HW / 128, BATCH);

    prep_w_k<<<128, b256>>>(qkv_pw, ln1_w, ln1_b, g1_w, ln2_w, ln2_b, g2_w);

    // --- MDTA ---
    ln_stats_k<<<dim3(16, BATCH), b256>>>(x, mu, rstd);
    gemm5<1, false, 128, 3><<<ggrid, b256, sm_128>>>(
        WqT, 0, WqP, 0, x, mu, rstd, rs, cb, nullptr, bufA, 384, 128);
    dwconv_k<<<dim3(8, BATCH * 384), b256>>>(bufA, qkv_dw, bufB, 384);
    attn_logits_k<<<dim3(ALOG_SEGS, 32), b256>>>(bufB);
    attn_finalize_k<<<32, b256>>>(temp);
    weff_k<<<dim3(4, 8), b256>>>(proj_w);
    gemm5<0, true, 128, 1><<<ggrid, b256, sm_128>>>(
        WeffT, (size_t)4 * 16384, Weff, 16384,
        bufB + (size_t)256 * HW, nullptr, nullptr, nullptr, nullptr,
        x, out, 128, 384);

    // --- GDFN ---
    ln_stats_k<<<dim3(16, BATCH), b256>>>(out, mu, rstd);
    gemm5<1, false, 128, 4><<<ggrid, b256, sm_128>>>(
        Wg1T, 0, Wg1P, 0, out, mu, rstd, rs + 384, cb + 384, nullptr, bufA, 512, 128);
    dwgate_k<<<dim3(8, BATCH * 256), b256>>>(bufA, gd_w, bufB);
    gemm5<0, true, 256, 1><<<ggrid, b256, sm_g2>>>(
        Wg2T, 0, Wg2P, 0, bufB, nullptr, nullptr, nullptr, nullptr,
        out, out, 128, 256);
}

// round 15
// speedup vs baseline: 1.1608x; 1.1608x over previous
#include <cuda_runtime.h>
#include <cuda_bf16.h>
#include <math.h>
#include <stdint.h>

// ---------------------------------------------------------------------------
// Problem constants (B=4, C=128, H=W=128, NH=8, d=16, GDFN hidden=512)
// ---------------------------------------------------------------------------
#define BATCH 4
#define CH    128
#define HW    16384
#define NHEAD 8
#define DHEAD 16
#define ALOG_SEGS 128

// ---------------------------------------------------------------------------
// Scratch (device globals)
// ---------------------------------------------------------------------------
__device__ float g_bufA[BATCH * 512 * HW];
__device__ float g_bufB[BATCH * 512 * HW];
__device__ float g_mu  [BATCH * HW];
__device__ float g_rstd[BATCH * HW];
__device__ float g_partS [32 * ALOG_SEGS * 256];
__device__ float g_partQ2[32 * ALOG_SEGS * 16];
__device__ float g_partK2[32 * ALOG_SEGS * 16];
__device__ float g_attn  [32 * 256];
__device__ float g_WqP [384 * 128];          // qkv weights, ln1-scaled, tf32-rounded
__device__ float g_Wg1P[512 * 128];          // g1 weights, ln2-scaled, tf32-rounded
__device__ float g_Wg2P[128 * 256];          // g2 weights, tf32-rounded
__device__ float g_rs  [896];
__device__ float g_cb  [896];
__device__ float g_Weff[BATCH * 128 * 128];  // per-batch proj*attn, tf32-rounded

// ---------------------------------------------------------------------------
// helpers
// ---------------------------------------------------------------------------
__device__ __forceinline__ uint32_t f2tf(float v)
{
    uint32_t r;
    asm("cvt.rna.tf32.f32 %0, %1;" : "=r"(r) : "f"(v));
    return r;
}

__device__ __forceinline__ void mma_tf32(float* d, const uint32_t* a, const uint32_t* b)
{
    asm volatile(
        "mma.sync.aligned.m16n8k8.row.col.f32.tf32.tf32.f32 "
        "{%0,%1,%2,%3},{%4,%5,%6,%7},{%8,%9},{%0,%1,%2,%3};"
        : "+f"(d[0]), "+f"(d[1]), "+f"(d[2]), "+f"(d[3])
        : "r"(a[0]), "r"(a[1]), "r"(a[2]), "r"(a[3]), "r"(b[0]), "r"(b[1]));
}

__device__ __forceinline__ void cp16(uint32_t dst_smem, const void* src)
{
    asm volatile("cp.async.ca.shared.global [%0], [%1], 16;" :: "r"(dst_smem), "l"(src));
}
__device__ __forceinline__ void cp_commit()
{
    asm volatile("cp.async.commit_group;");
}
template <int N>
__device__ __forceinline__ void cp_wait()
{
    asm volatile("cp.async.wait_group %0;" :: "n"(N));
}

__device__ __forceinline__ float gelu_exact(float v)
{
    return 0.5f * v * (1.f + erff(v * 0.70710678118654752440f));
}

// ---------------------------------------------------------------------------
// 0a) Weight prep: scale by LN weight, tf32-round, rowsum/const-bias; pack g2.
// ---------------------------------------------------------------------------
__global__ __launch_bounds__(256) void prep_w_k(const float* __restrict__ qkv_pw,
                                                const float* __restrict__ ln1w,
                                                const float* __restrict__ ln1b,
                                                const float* __restrict__ g1w,
                                                const float* __restrict__ ln2w,
                                                const float* __restrict__ ln2b,
                                                const float* __restrict__ g2w)
{
    int row  = blockIdx.x * 8 + (threadIdx.x >> 5);
    int lane = threadIdx.x & 31;

    if (row < 896) {
        const float *W, *lw, *lb;
        float* Wp;
        if (row < 384) { W = qkv_pw + (size_t)row * 128; lw = ln1w; lb = ln1b; Wp = g_WqP + (size_t)row * 128; }
        else           { W = g1w + (size_t)(row - 384) * 128; lw = ln2w; lb = ln2b; Wp = g_Wg1P + (size_t)(row - 384) * 128; }
        float rs = 0.f, cb = 0.f;
#pragma unroll
        for (int t = 0; t < 4; t++) {
            int c = lane + t * 32;
            float w = W[c];
            float wp = __uint_as_float(f2tf(w * lw[c]));
            Wp[c] = wp;
            rs += wp;
            cb += w * lb[c];
        }
#pragma unroll
        for (int o = 16; o > 0; o >>= 1) {
            rs += __shfl_xor_sync(0xffffffffu, rs, o);
            cb += __shfl_xor_sync(0xffffffffu, cb, o);
        }
        if (lane == 0) { g_rs[row] = rs; g_cb[row] = cb; }
    } else {
        int r = row - 896;
#pragma unroll
        for (int t = 0; t < 8; t++) {
            int c = lane + t * 32;
            g_Wg2P[r * 256 + c] = __uint_as_float(f2tf(g2w[r * 256 + c]));
        }
    }
}

// ---------------------------------------------------------------------------
// 0b) Per-pixel LayerNorm stats (input x only; GDFN stats come from MODE 3)
// ---------------------------------------------------------------------------
__global__ __launch_bounds__(256) void ln_stats_k(const float* __restrict__ x,
                                                  float* __restrict__ mu,
                                                  float* __restrict__ rstd)
{
    int b  = blockIdx.y;
    int n4 = blockIdx.x * 256 + threadIdx.x;
    const float4* xb = (const float4*)(x + (size_t)b * CH * HW) + n4;
    float4 s  = make_float4(0.f, 0.f, 0.f, 0.f);
    float4 s2 = make_float4(0.f, 0.f, 0.f, 0.f);
#pragma unroll 8
    for (int c = 0; c < CH; c++) {
        float4 v = xb[(size_t)c * (HW / 4)];
        s.x += v.x; s.y += v.y; s.z += v.z; s.w += v.w;
        s2.x = fmaf(v.x, v.x, s2.x); s2.y = fmaf(v.y, v.y, s2.y);
        s2.z = fmaf(v.z, v.z, s2.z); s2.w = fmaf(v.w, v.w, s2.w);
    }
    float4 m, r;
    m.x = s.x * (1.f / CH); m.y = s.y * (1.f / CH);
    m.z = s.z * (1.f / CH); m.w = s.w * (1.f / CH);
    r.x = rsqrtf(s2.x * (1.f / CH) - m.x * m.x + 1e-5f);
    r.y = rsqrtf(s2.y * (1.f / CH) - m.y * m.y + 1e-5f);
    r.z = rsqrtf(s2.z * (1.f / CH) - m.z * m.z + 1e-5f);
    r.w = rsqrtf(s2.w * (1.f / CH) - m.w * m.w + 1e-5f);
    *(float4*)&mu  [b * HW + n4 * 4] = m;
    *(float4*)&rstd[b * HW + n4 * 4] = r;
}

// ---------------------------------------------------------------------------
// 1) tf32 GEMM: 128x128x16 tiles, 256 threads, cp.async 3-buffer pipeline.
//    MODE 0: plain   MODE 1: LN-in-epilogue (mu/rstd from global)
//    MODE 3: plain + residual + LN-stats-out (muout/rstdout; needs OC=128/1 tile)
// ---------------------------------------------------------------------------
#define BM  128
#define BN  128
#define BK  16
#define BKP 20
#define BNP 136

template <int MODE, bool RESID>
__global__ __launch_bounds__(256) void gemm_tc(
    const float* __restrict__ W,      // (OC, K) row-major (per-batch via wbstride)
    const float* __restrict__ X,      // (B, XCH, HW)
    const float* __restrict__ mu,     // MODE 1 in; MODE 3 out
    const float* __restrict__ rstd,   // MODE 1 in; MODE 3 out
    const float* __restrict__ rsum,   // MODE 1
    const float* __restrict__ cbias,  // MODE 1
    const float* __restrict__ resid,
    float* __restrict__ out,          // (B, OC, HW)
    int OC, int K, int XCH, int wbstride)
{
    __shared__ uint32_t Ws[3][BM * BKP];
    __shared__ uint32_t Xs[3][BK * BNP];

    const int b    = blockIdx.z;
    const int n0   = blockIdx.x * BN;
    const int oc0  = blockIdx.y * BM;
    const int tid  = threadIdx.x;
    const int warp = tid >> 5;
    const int lane = tid & 31;
    const int wm   = warp >> 2;
    const int wn   = warp & 3;
    const int gid  = lane >> 2;
    const int tig  = lane & 3;

    const float* Wb = W + (size_t)b * wbstride;
    const float* Xb = X + (size_t)b * XCH * HW;

    const uint32_t ws_base = (uint32_t)__cvta_generic_to_shared(&Ws[0][0]);
    const uint32_t xs_base = (uint32_t)__cvta_generic_to_shared(&Xs[0][0]);

    const int wrow = tid >> 2, wcc = (tid & 3) << 2;
    const int xrow = tid >> 5, xcc = (tid & 31) << 2;

    float acc[4][4][4];
#pragma unroll
    for (int mt = 0; mt < 4; mt++)
#pragma unroll
        for (int nt = 0; nt < 4; nt++)
#pragma unroll
            for (int r = 0; r < 4; r++) acc[mt][nt][r] = 0.f;

    auto issue = [&](int s) {
        int buf = s % 3;
        int k0  = s * BK;
        cp16(ws_base + (uint32_t)(buf * (BM * BKP) + wrow * BKP + wcc) * 4,
             &Wb[(size_t)(oc0 + wrow) * K + k0 + wcc]);
        cp16(ws_base + (uint32_t)(buf * (BM * BKP) + (wrow + 64) * BKP + wcc) * 4,
             &Wb[(size_t)(oc0 + wrow + 64) * K + k0 + wcc]);
        cp16(xs_base + (uint32_t)(buf * (BK * BNP) + xrow * BNP + xcc) * 4,
             &Xb[(size_t)(k0 + xrow) * HW + n0 + xcc]);
        cp16(xs_base + (uint32_t)(buf * (BK * BNP) + (xrow + 8) * BNP + xcc) * 4,
             &Xb[(size_t)(k0 + xrow + 8) * HW + n0 + xcc]);
        cp_commit();
    };

    auto compute = [&](int s) {
        int buf = s % 3;
#pragma unroll
        for (int ks = 0; ks < 2; ks++) {
            uint32_t afr[4][4], bfr[4][2];
#pragma unroll
            for (int mt = 0; mt < 4; mt++) {
                int r = wm * 64 + mt * 16 + gid;
                int c = ks * 8 + tig;
                afr[mt][0] = Ws[buf][r * BKP + c];
                afr[mt][1] = Ws[buf][(r + 8) * BKP + c];
                afr[mt][2] = Ws[buf][r * BKP + c + 4];
                afr[mt][3] = Ws[buf][(r + 8) * BKP + c + 4];
            }
#pragma unroll
            for (int nt = 0; nt < 4; nt++) {
                int col = wn * 32 + nt * 8 + gid;
                bfr[nt][0] = Xs[buf][(ks * 8 + tig) * BNP + col];
                bfr[nt][1] = Xs[buf][(ks * 8 + tig + 4) * BNP + col];
            }
#pragma unroll
            for (int mt = 0; mt < 4; mt++)
#pragma unroll
                for (int nt = 0; nt < 4; nt++)
                    mma_tf32(acc[mt][nt], afr[mt], bfr[nt]);
        }
    };

    const int NS = K >> 4;
    issue(0);
    issue(1);

    for (int s = 0; s < NS; s++) {
        if (s + 2 < NS) cp_wait<1>(); else cp_wait<0>();
        __syncthreads();
        compute(s);
        if (s + 2 < NS) issue(s + 2);
    }

    if (MODE == 3) {
        // ---- residual-added output + LN stats of the result ----
        __syncthreads();                       // all compute done; reuse Ws
        float* colS  = (float*)&Ws[0][0];      // [16][128]
        float* colS2 = colS + 16 * 128;        // [16][128]   (16KB <= 30.7KB)
        float ps[4][2], ps2[4][2];
#pragma unroll
        for (int nt = 0; nt < 4; nt++) { ps[nt][0] = ps[nt][1] = ps2[nt][0] = ps2[nt][1] = 0.f; }

#pragma unroll
        for (int mt = 0; mt < 4; mt++) {
            int ocl0 = wm * 64 + mt * 16 + gid;
#pragma unroll
            for (int nt = 0; nt < 4; nt++) {
                int nl = wn * 32 + nt * 8 + tig * 2;
                size_t base0 = ((size_t)b * OC + ocl0) * HW + n0 + nl;
                size_t base1 = ((size_t)b * OC + ocl0 + 8) * HW + n0 + nl;
                float2 q0 = *(const float2*)&resid[base0];
                float2 q1 = *(const float2*)&resid[base1];
                float z00 = acc[mt][nt][0] + q0.x;
                float z01 = acc[mt][nt][1] + q0.y;
                float z10 = acc[mt][nt][2] + q1.x;
                float z11 = acc[mt][nt][3] + q1.y;
                *(float2*)&out[base0] = make_float2(z00, z01);
                *(float2*)&out[base1] = make_float2(z10, z11);
                ps [nt][0] += z00 + z10;        ps [nt][1] += z01 + z11;
                ps2[nt][0] = fmaf(z00, z00, fmaf(z10, z10, ps2[nt][0]));
                ps2[nt][1] = fmaf(z01, z01, fmaf(z11, z11, ps2[nt][1]));
            }
        }
        int slot = wm * 8 + gid;               // 0..15
#pragma unroll
        for (int nt = 0; nt < 4; nt++) {
#pragma unroll
            for (int c = 0; c < 2; c++) {
                int nl = wn * 32 + nt * 8 + tig * 2 + c;
                colS [slot * 128 + nl] = ps [nt][c];
                colS2[slot * 128 + nl] = ps2[nt][c];
            }
        }
        __syncthreads();
        if (tid < 128) {
            float s = 0.f, s2 = 0.f;
#pragma unroll
            for (int j = 0; j < 16; j++) {
                s  += colS [j * 128 + tid];
                s2 += colS2[j * 128 + tid];
            }
            float m   = s * (1.f / 128.f);
            float var = s2 * (1.f / 128.f) - m * m;
            ((float*)mu)  [b * HW + n0 + tid] = m;
            ((float*)rstd)[b * HW + n0 + tid] = rsqrtf(var + 1e-5f);
        }
        return;
    }

    // --- epilogue (MODE 0/1) ---
#pragma unroll
    for (int mt = 0; mt < 4; mt++) {
        int ocl0 = wm * 64 + mt * 16 + gid;
        float rs0 = 0.f, rs1 = 0.f, cb0 = 0.f, cb1 = 0.f;
        if (MODE == 1) {
            rs0 = rsum[oc0 + ocl0];  rs1 = rsum[oc0 + ocl0 + 8];
            cb0 = cbias[oc0 + ocl0]; cb1 = cbias[oc0 + ocl0 + 8];
        }
#pragma unroll
        for (int nt = 0; nt < 4; nt++) {
            int nl = wn * 32 + nt * 8 + tig * 2;
            size_t base0 = ((size_t)b * OC + oc0 + ocl0) * HW + n0 + nl;
            size_t base1 = ((size_t)b * OC + oc0 + ocl0 + 8) * HW + n0 + nl;
            float2 r0 = make_float2(acc[mt][nt][0], acc[mt][nt][1]);
            float2 r1 = make_float2(acc[mt][nt][2], acc[mt][nt][3]);
            if (MODE == 1) {
                float2 m2 = *(const float2*)&mu  [b * HW + n0 + nl];
                float2 d2 = *(const float2*)&rstd[b * HW + n0 + nl];
                r0.x = d2.x * (r0.x - m2.x * rs0) + cb0;
                r0.y = d2.y * (r0.y - m2.y * rs0) + cb0;
                r1.x = d2.x * (r1.x - m2.x * rs1) + cb1;
                r1.y = d2.y * (r1.y - m2.y * rs1) + cb1;
            }
            if (RESID) {
                float2 q0 = *(const float2*)&resid[base0];
                float2 q1 = *(const float2*)&resid[base1];
                r0.x += q0.x; r0.y += q0.y;
                r1.x += q1.x; r1.y += q1.y;
            }
            *(float2*)&out[base0] = r0;
            *(float2*)&out[base1] = r1;
        }
    }
}

// ---------------------------------------------------------------------------
// 2) Depthwise 3x3 conv, full-width 128x32 tiles, float4 I/O.
//    grid (4 ytiles, B*CHN planes), 256 threads.
// ---------------------------------------------------------------------------
__global__ __launch_bounds__(256) void dwconv_k(const float* __restrict__ in,
                                                const float* __restrict__ wd,
                                                float* __restrict__ out,
                                                int CHN)
{
    __shared__ float t[34][136];     // rows y0-1..y0+32, data at cols [4..131]
    int plane = blockIdx.y;
    int ch    = plane % CHN;
    size_t base = (size_t)plane * HW;
    int y0  = blockIdx.x * 32;
    int tid = threadIdx.x;

    if (tid < 68) t[tid >> 1][3 + (tid & 1) * 129] = 0.f;
#pragma unroll
    for (int i = tid; i < 1088; i += 256) {   // 34 rows x 32 float4
        int r = i >> 5, c4 = (i & 31) << 2;
        int gy = y0 - 1 + r;
        float4 v = make_float4(0.f, 0.f, 0.f, 0.f);
        if (gy >= 0 && gy < 128) v = *(const float4*)&in[base + gy * 128 + c4];
        *(float4*)&t[r][4 + c4] = v;
    }
    __syncthreads();

    float w[9];
#pragma unroll
    for (int j = 0; j < 9; j++) w[j] = wd[ch * 9 + j];

    int x4 = (tid & 31) << 2;
    int r0 = tid >> 5;
#pragma unroll
    for (int rr = 0; rr < 32; rr += 8) {
        int row = r0 + rr;
        float4 o = make_float4(0.f, 0.f, 0.f, 0.f);
#pragma unroll
        for (int dy = 0; dy < 3; dy++) {
            const float* tr = &t[row + dy][4 + x4];
            float m0 = tr[-1], m1 = tr[0], m2 = tr[1], m3 = tr[2], m4 = tr[3], m5 = tr[4];
            float a = w[dy * 3 + 0], bw = w[dy * 3 + 1], c = w[dy * 3 + 2];
            o.x = fmaf(a, m0, fmaf(bw, m1, fmaf(c, m2, o.x)));
            o.y = fmaf(a, m1, fmaf(bw, m2, fmaf(c, m3, o.y)));
            o.z = fmaf(a, m2, fmaf(bw, m3, fmaf(c, m4, o.z)));
            o.w = fmaf(a, m3, fmaf(bw, m4, fmaf(c, m5, o.w)));
        }
        *(float4*)&out[base + (y0 + row) * 128 + x4] = o;
    }
}

// ---------------------------------------------------------------------------
// 2b) GDFN: dwconv of x1/x2 + gelu gate, fused. 128x32 tiles. grid (4, B*256).
// ---------------------------------------------------------------------------
__global__ __launch_bounds__(256) void dwgate_k(const float* __restrict__ in,
                                                const float* __restrict__ wd,
                                                float* __restrict__ out)
{
    __shared__ float t1[34][136];
    __shared__ float t2[34][136];
    int plane = blockIdx.y;
    int b  = plane >> 8, ch = plane & 255;
    size_t base1 = ((size_t)b * 512 + ch) * HW;
    size_t base2 = ((size_t)b * 512 + 256 + ch) * HW;
    size_t baseo = ((size_t)b * 256 + ch) * HW;
    int y0  = blockIdx.x * 32;
    int tid = threadIdx.x;

    if (tid < 68) {
        t1[tid >> 1][3 + (tid & 1) * 129] = 0.f;
        t2[tid >> 1][3 + (tid & 1) * 129] = 0.f;
    }
#pragma unroll
    for (int i = tid; i < 1088; i += 256) {
        int r = i >> 5, c4 = (i & 31) << 2;
        int gy = y0 - 1 + r;
        float4 v1 = make_float4(0.f, 0.f, 0.f, 0.f);
        float4 v2 = make_float4(0.f, 0.f, 0.f, 0.f);
        if (gy >= 0 && gy < 128) {
            v1 = *(const float4*)&in[base1 + gy * 128 + c4];
            v2 = *(const float4*)&in[base2 + gy * 128 + c4];
        }
        *(float4*)&t1[r][4 + c4] = v1;
        *(float4*)&t2[r][4 + c4] = v2;
    }
    __syncthreads();

    float wA[9], wB[9];
#pragma unroll
    for (int j = 0; j < 9; j++) { wA[j] = wd[ch * 9 + j]; wB[j] = wd[(256 + ch) * 9 + j]; }

    int x4 = (tid & 31) << 2;
    int r0 = tid >> 5;
#pragma unroll
    for (int rr = 0; rr < 32; rr += 8) {
        int row = r0 + rr;
        float4 o1 = make_float4(0.f, 0.f, 0.f, 0.f);
        float4 o2 = make_float4(0.f, 0.f, 0.f, 0.f);
#pragma unroll
        for (int dy = 0; dy < 3; dy++) {
            {
                const float* tr = &t1[row + dy][4 + x4];
                float m0 = tr[-1], m1 = tr[0], m2 = tr[1], m3 = tr[2], m4 = tr[3], m5 = tr[4];
                float a = wA[dy * 3 + 0], bw = wA[dy * 3 + 1], c = wA[dy * 3 + 2];
                o1.x = fmaf(a, m0, fmaf(bw, m1, fmaf(c, m2, o1.x)));
                o1.y = fmaf(a, m1, fmaf(bw, m2, fmaf(c, m3, o1.y)));
                o1.z = fmaf(a, m2, fmaf(bw, m3, fmaf(c, m4, o1.z)));
                o1.w = fmaf(a, m3, fmaf(bw, m4, fmaf(c, m5, o1.w)));
            }
            {
                const float* tr = &t2[row + dy][4 + x4];
                float m0 = tr[-1], m1 = tr[0], m2 = tr[1], m3 = tr[2], m4 = tr[3], m5 = tr[4];
                float a = wB[dy * 3 + 0], bw = wB[dy * 3 + 1], c = wB[dy * 3 + 2];
                o2.x = fmaf(a, m0, fmaf(bw, m1, fmaf(c, m2, o2.x)));
                o2.y = fmaf(a, m1, fmaf(bw, m2, fmaf(c, m3, o2.y)));
                o2.z = fmaf(a, m2, fmaf(bw, m3, fmaf(c, m4, o2.z)));
                o2.w = fmaf(a, m3, fmaf(bw, m4, fmaf(c, m5, o2.w)));
            }
        }
        float4 g;
        g.x = gelu_exact(o1.x) * o2.x;
        g.y = gelu_exact(o1.y) * o2.y;
        g.z = gelu_exact(o1.z) * o2.z;
        g.w = gelu_exact(o1.w) * o2.w;
        *(float4*)&out[baseo + (y0 + row) * 128 + x4] = g;
    }
}

// ---------------------------------------------------------------------------
// 3) Attention logits (float4 loads) + fused sq-norm partials
// ---------------------------------------------------------------------------
__global__ __launch_bounds__(256) void attn_logits_k(const float* __restrict__ qkv)
{
    int seg = blockIdx.x;
    int bh  = blockIdx.y;
    int b = bh >> 3, h = bh & 7;
    const float* qb = qkv + ((size_t)b * 384 + h * DHEAD) * HW + seg * 128;
    const float* kb = qkv + ((size_t)b * 384 + 128 + h * DHEAD) * HW + seg * 128;

    __shared__ __align__(16) float qs[16][132];
    __shared__ __align__(16) float ks[16][132];

    int tid = threadIdx.x;
#pragma unroll
    for (int t = 0; t < 2; t++) {
        int idx = tid + t * 256;
        int row = idx >> 5, c4 = (idx & 31) << 2;
        *(float4*)&qs[row][c4] = *(const float4*)&qb[(size_t)row * HW + c4];
        *(float4*)&ks[row][c4] = *(const float4*)&kb[(size_t)row * HW + c4];
    }
    __syncthreads();

    int i = tid >> 4, j = tid & 15;
    bool diag = (i == j);
    const float4* q4 = (const float4*)&qs[i][0];
    const float4* k4 = (const float4*)&ks[j][0];
    float acc = 0.f, q2 = 0.f, k2 = 0.f;
#pragma unroll 8
    for (int n4 = 0; n4 < 32; n4++) {
        float4 a = q4[n4];
        float4 c = k4[n4];
        acc = fmaf(a.x, c.x, acc); acc = fmaf(a.y, c.y, acc);
        acc = fmaf(a.z, c.z, acc); acc = fmaf(a.w, c.w, acc);
        if (diag) {
            q2 = fmaf(a.x, a.x, q2); q2 = fmaf(a.y, a.y, q2);
            q2 = fmaf(a.z, a.z, q2); q2 = fmaf(a.w, a.w, q2);
            k2 = fmaf(c.x, c.x, k2); k2 = fmaf(c.y, c.y, k2);
            k2 = fmaf(c.z, c.z, k2); k2 = fmaf(c.w, c.w, k2);
        }
    }

    int slot = bh * ALOG_SEGS + seg;
    g_partS[(size_t)slot * 256 + tid] = acc;
    if (diag) {
        g_partQ2[slot * 16 + i] = q2;
        g_partK2[slot * 16 + i] = k2;
    }
}

// ---------------------------------------------------------------------------
// 4) Finalize: reduce segments, l2norm scale, temperature, softmax
// ---------------------------------------------------------------------------
__global__ __launch_bounds__(256) void attn_finalize_k(const float* __restrict__ temp)
{
    int bh = blockIdx.x;
    int h = bh & 7;
    int i = threadIdx.x >> 4, j = threadIdx.x & 15;

    float s = 0.f, q2 = 0.f, k2 = 0.f;
    for (int seg = 0; seg < ALOG_SEGS; seg++) {
        int slot = bh * ALOG_SEGS + seg;
        s  += g_partS [(size_t)slot * 256 + threadIdx.x];
        q2 += g_partQ2[slot * 16 + i];
        k2 += g_partK2[slot * 16 + j];
    }
    float rq = 1.f / fmaxf(sqrtf(q2), 1e-12f);
    float rk = 1.f / fmaxf(sqrtf(k2), 1e-12f);
    s = s * rq * rk * temp[h];

    float m = s;
    m = fmaxf(m, __shfl_xor_sync(0xffffffffu, m, 8, 16));
    m = fmaxf(m, __shfl_xor_sync(0xffffffffu, m, 4, 16));
    m = fmaxf(m, __shfl_xor_sync(0xffffffffu, m, 2, 16));
    m = fmaxf(m, __shfl_xor_sync(0xffffffffu, m, 1, 16));
    float e = expf(s - m);
    float sum = e;
    sum += __shfl_xor_sync(0xffffffffu, sum, 8, 16);
    sum += __shfl_xor_sync(0xffffffffu, sum, 4, 16);
    sum += __shfl_xor_sync(0xffffffffu, sum, 2, 16);
    sum += __shfl_xor_sync(0xffffffffu, sum, 1, 16);
    g_attn[bh * 256 + threadIdx.x] = e / sum;
}

// ---------------------------------------------------------------------------
// 5) Effective proj weights (tf32-rounded)
// ---------------------------------------------------------------------------
__global__ __launch_bounds__(256) void weff_k(const float* __restrict__ proj_w)
{
    int b = blockIdx.x, h = blockIdx.y;
    __shared__ float at[16][16];
    __shared__ float pw[128][16];
    int tid = threadIdx.x;

    at[tid >> 4][tid & 15] = g_attn[(b * 8 + h) * 256 + tid];
#pragma unroll
    for (int t = 0; t < 8; t++) {
        int idx = tid + t * 256;
        int o = idx >> 4, i = idx & 15;
        pw[o][i] = proj_w[o * 128 + h * 16 + i];
    }
    __syncthreads();

#pragma unroll
    for (int t = 0; t < 8; t++) {
        int idx = tid + t * 256;
        int o = idx >> 4, e = idx & 15;
        float s = 0.f;
#pragma unroll
        for (int i = 0; i < 16; i++) s = fmaf(pw[o][i], at[i][e], s);
        g_Weff[((size_t)b * 128 + o) * 128 + h * 16 + e] = __uint_as_float(f2tf(s));
    }
}

// ---------------------------------------------------------------------------
// Launch
// ---------------------------------------------------------------------------
extern "C" void kernel_launch(void* const* d_in, const int* in_sizes, int n_in,
                              void* d_out, int out_size)
{
    const float* x      = (const float*)d_in[0];
    const float* ln1_w  = (const float*)d_in[1];
    const float* ln1_b  = (const float*)d_in[2];
    const float* temp   = (const float*)d_in[3];
    const float* qkv_pw = (const float*)d_in[4];
    const float* qkv_dw = (const float*)d_in[5];
    const float* proj_w = (const float*)d_in[6];
    const float* ln2_w  = (const float*)d_in[7];
    const float* ln2_b  = (const float*)d_in[8];
    const float* g1_w   = (const float*)d_in[9];
    const float* gd_w   = (const float*)d_in[10];
    const float* g2_w   = (const float*)d_in[11];
    float* out = (float*)d_out;

    float *bufA, *bufB, *WqP, *Wg1P, *Wg2P, *rs, *cb, *Weff, *mu, *rstd;
    cudaGetSymbolAddress((void**)&bufA, g_bufA);
    cudaGetSymbolAddress((void**)&bufB, g_bufB);
    cudaGetSymbolAddress((void**)&WqP,  g_WqP);
    cudaGetSymbolAddress((void**)&Wg1P, g_Wg1P);
    cudaGetSymbolAddress((void**)&Wg2P, g_Wg2P);
    cudaGetSymbolAddress((void**)&rs,   g_rs);
    cudaGetSymbolAddress((void**)&cb,   g_cb);
    cudaGetSymbolAddress((void**)&Weff, g_Weff);
    cudaGetSymbolAddress((void**)&mu,   g_mu);
    cudaGetSymbolAddress((void**)&rstd, g_rstd);

    dim3 b256(256);

    prep_w_k<<<128, b256>>>(qkv_pw, ln1_w, ln1_b, g1_w, ln2_w, ln2_b, g2_w);

    // --- MDTA ---
    ln_stats_k<<<dim3(16, BATCH), b256>>>(x, mu, rstd);
    gemm_tc<1, false><<<dim3(HW / BN, 384 / BM, BATCH), b256>>>(
        WqP, x, mu, rstd, rs, cb, nullptr, bufA, 384, 128, 128, 0);
    dwconv_k<<<dim3(4, BATCH * 384), b256>>>(bufA, qkv_dw, bufB, 384);
    attn_logits_k<<<dim3(ALOG_SEGS, 32), b256>>>(bufB);
    attn_finalize_k<<<32, b256>>>(temp);
    weff_k<<<dim3(4, 8), b256>>>(proj_w);
    // x2 = x + Weff_b * v ; emits LN stats of x2 (kills ln_stats #2)
    gemm_tc<3, true><<<dim3(HW / BN, 1, BATCH), b256>>>(
        Weff, bufB + (size_t)256 * HW, mu, rstd, nullptr, nullptr,
        x, out, 128, 128, 384, 128 * 128);

    // --- GDFN ---
    gemm_tc<1, false><<<dim3(HW / BN, 512 / BM, BATCH), b256>>>(
        Wg1P, out, mu, rstd, rs + 384, cb + 384, nullptr, bufA, 512, 128, 128, 0);
    dwgate_k<<<dim3(4, BATCH * 256), b256>>>(bufA, gd_w, bufB);
    gemm_tc<0, true><<<dim3(HW / BN, 1, BATCH), b256>>>(
        Wg2P, bufB, nullptr, nullptr, nullptr, nullptr,
        out, out, 128, 256, 256, 0);
}